// round 12
// baseline (speedup 1.0000x reference)
#include <cuda_runtime.h>
#include <cstdint>

#define D_      32
#define K_      40
#define DTOT_   64
#define Bb      5.0f
#define LUTN_   128

// Transposed tables: [bin][dim] — bank depends only on dim (conflict-free gathers).
__device__ float4   g_At  [K_ * D_];     // {mcw = -cumw*ibw, ibw, ch, bh}
__device__ float2   g_B2t [K_ * D_];     // {d0, d1}
__device__ unsigned g_lutp[LUTN_ * D_];  // fp32 edge, idx in low 6 mantissa bits
__device__ int      g_colmap[DTOT_];
__device__ int      g_upper;             // any spline dim in cols 32..63?

#define FULLM 0xffffffffu
__device__ __forceinline__ float warp_max(float v) {
#pragma unroll
    for (int o = 16; o; o >>= 1) v = fmaxf(v, __shfl_xor_sync(FULLM, v, o));
    return v;
}
__device__ __forceinline__ float warp_sum(float v) {
#pragma unroll
    for (int o = 16; o; o >>= 1) v += __shfl_xor_sync(FULLM, v, o);
    return v;
}
__device__ __forceinline__ float warp_scan(float v, int lane) {
#pragma unroll
    for (int o = 1; o < 32; o <<= 1) {
        float t = __shfl_up_sync(FULLM, v, o);
        if (lane >= o) v += t;
    }
    return v;
}

// Warp-per-dim precompute (32 warps).
__global__ void __launch_bounds__(1024)
precompute_tables(const float* __restrict__ w,
                  const float* __restrict__ h,
                  const float* __restrict__ d,
                  const int*   __restrict__ nodes) {
    __shared__ float scumw[D_][K_ + 1];
    const int tid = threadIdx.x, lane = tid & 31, j = tid >> 5;

    if (tid < DTOT_) g_colmap[tid] = -1;
    __syncthreads();
    if (tid < D_) g_colmap[nodes[tid]] = tid;
    __syncthreads();
    if (tid == 0) {
        int f = 0;
        for (int c = 32; c < DTOT_; c++) f |= (g_colmap[c] >= 0) ? 1 : 0;
        g_upper = f;
    }

    // widths
    const float w0 = w[j * K_ + lane];
    const float w1 = (lane < 8) ? w[j * K_ + 32 + lane] : -1e30f;
    float m = warp_max(fmaxf(w0, w1));
    const float e0 = expf(w0 - m);
    const float e1 = (lane < 8) ? expf(w1 - m) : 0.0f;
    const float scl = (2.0f * Bb) / warp_sum(e0 + e1);
    const float bw0 = e0 * scl, bw1 = e1 * scl;
    float s0 = warp_scan(bw0, lane);
    const float tot0 = __shfl_sync(FULLM, s0, 31);
    float s1 = warp_scan(bw1, lane) + tot0;
    const float cw0 = -Bb + s0 - bw0, cw0n = -Bb + s0;
    const float cw1 = -Bb + s1 - bw1, cw1n = -Bb + s1;

    // heights
    const float h0 = h[j * K_ + lane];
    const float h1 = (lane < 8) ? h[j * K_ + 32 + lane] : -1e30f;
    m = warp_max(fmaxf(h0, h1));
    const float f0 = expf(h0 - m);
    const float f1 = (lane < 8) ? expf(h1 - m) : 0.0f;
    const float scl2 = (2.0f * Bb) / warp_sum(f0 + f1);
    const float bh0 = f0 * scl2, bh1 = f1 * scl2;
    float t0 = warp_scan(bh0, lane);
    const float htot0 = __shfl_sync(FULLM, t0, 31);
    float t1 = warp_scan(bh1, lane) + htot0;
    const float ch0 = -Bb + t0 - bh0;
    const float ch1 = -Bb + t1 - bh1;

    // derivatives dv(i) = (i==0||i==K)?1:softplus(d[i-1])
    const float dva0 = (lane == 0) ? 1.0f : log1pf(expf(d[j * (K_ - 1) + lane - 1]));
    const float dvb0 = log1pf(expf(d[j * (K_ - 1) + lane]));
    float dva1 = 0.f, dvb1 = 0.f;
    if (lane < 8) {
        const int i = 32 + lane;
        dva1 = log1pf(expf(d[j * (K_ - 1) + i - 1]));
        dvb1 = (i + 1 == K_) ? 1.0f : log1pf(expf(d[j * (K_ - 1) + i]));
    }

    // transposed stores: [bin][dim]; A.x = -cumw*ibw for 1-FFMA theta
    {
        const float ibw = 1.0f / bw0;
        g_At [lane * D_ + j] = make_float4(-cw0 * ibw, ibw, ch0, bh0);
        g_B2t[lane * D_ + j] = make_float2(dva0, dvb0);
        scumw[j][lane] = cw0;
    }
    if (lane < 8) {
        const int i = 32 + lane;
        const float ibw = 1.0f / bw1;
        g_At [i * D_ + j] = make_float4(-cw1 * ibw, ibw, ch1, bh1);
        g_B2t[i * D_ + j] = make_float2(dva1, dvb1);
        scumw[j][i] = cw1;
        if (i == K_ - 1) scumw[j][K_] = cw1n;
    }
    __syncwarp();

    // LUT: entry[m][j] = fp32(cumw[idx+1]) | idx (low 6 bits); NaN edge on last bin.
    #pragma unroll
    for (int c = 0; c < 4; c++) {
        const int mm = lane * 4 + c;
        const float xm = -Bb + (2.0f * Bb) * ((float)mm / (float)LUTN_);
        int lo = 0, hi = K_;
        while (hi - lo > 1) {
            const int mid = (lo + hi) >> 1;
            if (scumw[j][mid] <= xm) lo = mid; else hi = mid;
        }
        unsigned bits;
        if (lo >= K_ - 1) {
            bits = (0x7fc00000u & ~63u) | (unsigned)(K_ - 1);
        } else {
            const float edge = scumw[j][lo + 1];
            bits = (__float_as_uint(edge) & ~63u) | (unsigned)lo;
        }
        g_lutp[mm * D_ + j] = bits;
    }
}

__device__ __forceinline__ void eval_one(
    float x, int jb, float lim,
    const float4* s_A, const float2* s_B2, const unsigned* s_lutp,
    float& y, float& acc)
{
    const float xc = fminf(fmaxf(x, -Bb), 4.9999995f);
    const int m = (int)fmaf(xc, (float)LUTN_ / (2.0f * Bb), (float)(LUTN_ / 2));
    const unsigned e = s_lutp[m * D_ + jb];
    int idx = (int)(e & 63u);
    const float edge = __uint_as_float(e & ~63u);
    idx += (xc >= edge);          // NaN edge on last bin => never increments

    const float4 A  = s_A [idx * D_ + jb];
    const float2 Bv = s_B2[idx * D_ + jb];
    const float ibw = A.y, bh = A.w;
    const float dlt = bh * ibw;
    const float theta = fmaf(xc, ibw, A.x);
    const float t2  = theta * theta;
    const float t1m = theta - t2;
    const float d0v = Bv.x, d1v = Bv.y;
    const float denom = fmaf(d0v + d1v - 2.0f * dlt, t1m, dlt);
    const float rd  = __fdividef(1.0f, denom);
    const float num = bh * fmaf(dlt, t2, d0v * t1m);
    const float ys  = fmaf(num, rd, A.z);
    const float omt = 1.0f - theta;
    const float At  = fmaf(d1v, t2, fmaf(2.0f * dlt, t1m, d0v * (omt * omt)));
    const float dr  = dlt * rd;
    const float ld  = __logf(dr * dr * At);

    const bool valid = fabsf(x) <= lim;
    y = valid ? ys : x;
    acc += valid ? ld : 0.0f;
}

// Dynamic smem: A(20480) B2(10240) lut(16384) colmap(256)
#define SM_A_ELE  (K_ * D_)
#define SM_B_OFF  (SM_A_ELE * 16)
#define SM_L_OFF  (SM_B_OFF + SM_A_ELE * 8)
#define SM_C_OFF  (SM_L_OFF + LUTN_ * D_ * 4)
#define SM_TOTAL  (SM_C_OFF + DTOT_ * 4)

#define SPLW 12   // spline warps per block
#define CPW  4    // copy warps per block
#define GRID 444

extern __shared__ unsigned char smem_raw[];

__global__ void __launch_bounds__(512, 3)
spline_kernel(const float* __restrict__ u,
              float* __restrict__ xout,
              float* __restrict__ logd,
              int N) {
    float4*   s_A      = (float4*)smem_raw;
    float2*   s_B2     = (float2*)(smem_raw + SM_B_OFF);
    unsigned* s_lutp   = (unsigned*)(smem_raw + SM_L_OFF);
    int*      s_colmap = (int*)(smem_raw + SM_C_OFF);

    for (int i = threadIdx.x; i < SM_A_ELE; i += blockDim.x) {
        s_A[i]  = g_At[i];
        s_B2[i] = g_B2t[i];
    }
    for (int i = threadIdx.x; i < LUTN_ * D_; i += blockDim.x)
        s_lutp[i] = g_lutp[i];
    if (threadIdx.x < DTOT_) s_colmap[threadIdx.x] = g_colmap[threadIdx.x];
    __syncthreads();

    const int lane = threadIdx.x & 31;
    const int warp = threadIdx.x >> 5;
    const int upper = g_upper;            // L2/const cached

    if (warp >= SPLW) {
        // ================= COPY WARPS: cols 32..63, float4 streaming ==========
        if (upper) return;                // generic fallback handled by spline warps
        const int cid  = blockIdx.x * CPW + (warp - SPLW);
        const int nC   = GRID * CPW;
        const long step = (long)nC * 16;  // rows per iteration across all copy warps
        const int r = lane >> 3;          // row-in-group 0..3
        const int q = lane & 7;           // float4 index within 32 identity cols

        long base = (long)cid * 16;
        const long off = (long)r * DTOT_ + 32 + q * 4;

        for (; base + 15 < N; base += step) {
            const float* src = u    + base * DTOT_ + off;
            float*       dst = xout + base * DTOT_ + off;
            const float4 v0 = *(const float4*)(src);
            const float4 v1 = *(const float4*)(src + 256);
            const float4 v2 = *(const float4*)(src + 512);
            const float4 v3 = *(const float4*)(src + 768);
            *(float4*)(dst)       = v0;
            *(float4*)(dst + 256) = v1;
            *(float4*)(dst + 512) = v2;
            *(float4*)(dst + 768) = v3;
        }
        // tail rows
        for (long row = base + r; row < N; row += 4) {
            const long o = row * DTOT_ + 32 + q * 4;
            *(float4*)(xout + o) = *(const float4*)(u + o);
        }
        return;
    }

    // ================= SPLINE WARPS ==========================================
    const int j0 = s_colmap[lane];
    const int jb0 = max(j0, 0);
    const float lim0 = (j0 >= 0) ? Bb : -1.0f;
    const bool do0 = __any_sync(FULLM, j0 >= 0);

    const int sid = blockIdx.x * SPLW + warp;
    const int nS  = GRID * SPLW;

    if (!upper) {
        // fast path: lower 32 cols only (4 rows per iteration)
        const long step  = (long)nS * 4;
        const long stepF = step * DTOT_;
        long row = (long)sid * 4;
        const float* pu = u    + row * DTOT_ + lane;
        float*       px = xout + row * DTOT_ + lane;
        float*       pl = logd + row;

        for (; row < N; row += step, pu += stepF, px += stepF, pl += step) {
            if (row + 3 < N) {
                const float a = pu[0], b = pu[64], c = pu[128], d = pu[192];
                float aa = 0.f, ab = 0.f, ac = 0.f, ad = 0.f;
                float ya = a, yb = b, yc = c, yd = d;
                if (do0) {
                    eval_one(a, jb0, lim0, s_A, s_B2, s_lutp, ya, aa);
                    eval_one(b, jb0, lim0, s_A, s_B2, s_lutp, yb, ab);
                    eval_one(c, jb0, lim0, s_A, s_B2, s_lutp, yc, ac);
                    eval_one(d, jb0, lim0, s_A, s_B2, s_lutp, yd, ad);
                }
                px[0] = ya; px[64] = yb; px[128] = yc; px[192] = yd;
                {
                    float v = (lane < 16) ? ab : aa;
                    float t = __shfl_xor_sync(FULLM, v, 16);
                    float rr = ((lane < 16) ? aa : ab) + t;
#pragma unroll
                    for (int o = 8; o; o >>= 1) rr += __shfl_xor_sync(FULLM, rr, o);
                    if (lane == 0)  pl[0] = rr;
                    if (lane == 16) pl[1] = rr;
                }
                {
                    float v = (lane < 16) ? ad : ac;
                    float t = __shfl_xor_sync(FULLM, v, 16);
                    float rr = ((lane < 16) ? ac : ad) + t;
#pragma unroll
                    for (int o = 8; o; o >>= 1) rr += __shfl_xor_sync(FULLM, rr, o);
                    if (lane == 0)  pl[2] = rr;
                    if (lane == 16) pl[3] = rr;
                }
            } else {
                for (int t = 0; t < 4 && row + t < N; t++) {
                    const float x0 = pu[t * 64];
                    float acc = 0.f, y0 = x0;
                    if (do0) eval_one(x0, jb0, lim0, s_A, s_B2, s_lutp, y0, acc);
                    px[t * 64] = y0;
#pragma unroll
                    for (int o = 16; o; o >>= 1) acc += __shfl_xor_sync(FULLM, acc, o);
                    if (lane == 0) pl[t] = acc;
                }
            }
        }
    } else {
        // generic path: both halves (2 rows per iteration); copy warps idle
        const int j1 = s_colmap[lane + 32];
        const int jb1 = max(j1, 0);
        const float lim1 = (j1 >= 0) ? Bb : -1.0f;
        const bool do1 = __any_sync(FULLM, j1 >= 0);

        const long step  = (long)nS * 2;
        const long stepF = step * DTOT_;
        long row = (long)sid * 2;
        const float* pu = u    + row * DTOT_ + lane;
        float*       px = xout + row * DTOT_ + lane;
        float*       pl = logd + row;

        for (; row < N; row += step, pu += stepF, px += stepF, pl += step) {
            const bool hb = row + 1 < N;
            const float a0 = pu[0],  a1 = pu[32];
            const float b0 = hb ? pu[64] : 0.f, b1 = hb ? pu[96] : 0.f;
            float aa = 0.f, ab = 0.f;
            float ya0 = a0, ya1 = a1, yb0 = b0, yb1 = b1;
            if (do0) {
                eval_one(a0, jb0, lim0, s_A, s_B2, s_lutp, ya0, aa);
                eval_one(b0, jb0, lim0, s_A, s_B2, s_lutp, yb0, ab);
            }
            if (do1) {
                eval_one(a1, jb1, lim1, s_A, s_B2, s_lutp, ya1, aa);
                eval_one(b1, jb1, lim1, s_A, s_B2, s_lutp, yb1, ab);
            }
            px[0] = ya0; px[32] = ya1;
            if (hb) { px[64] = yb0; px[96] = yb1; }
            float v = (lane < 16) ? ab : aa;
            float t = __shfl_xor_sync(FULLM, v, 16);
            float rr = ((lane < 16) ? aa : ab) + t;
#pragma unroll
            for (int o = 8; o; o >>= 1) rr += __shfl_xor_sync(FULLM, rr, o);
            if (lane == 0) pl[0] = rr;
            if (lane == 16 && hb) pl[1] = rr;
        }
    }
}

extern "C" void kernel_launch(void* const* d_in, const int* in_sizes, int n_in,
                              void* d_out, int out_size) {
    const float* u     = (const float*)d_in[0];
    const float* w     = (const float*)d_in[1];
    const float* h     = (const float*)d_in[2];
    const float* d     = (const float*)d_in[3];
    const int*   nodes = (const int*)  d_in[4];

    const int N = out_size - in_sizes[0];
    float* xout = (float*)d_out;
    float* logd = xout + (size_t)N * DTOT_;

    static int smem_set = 0;
    if (!smem_set) {
        cudaFuncSetAttribute(spline_kernel,
                             cudaFuncAttributeMaxDynamicSharedMemorySize, SM_TOTAL);
        smem_set = 1;
    }

    precompute_tables<<<1, 1024>>>(w, h, d, nodes);
    spline_kernel<<<GRID, 512, SM_TOTAL>>>(u, xout, logd, N);
}